// round 15
// baseline (speedup 1.0000x reference)
#include <cuda_runtime.h>
#include <cuda_fp16.h>
#include <cstdint>
#include <math.h>

#define N_ROWS 65536
#define D      256
#define K      2048

// ---------------- device scratch ----------------
__device__ __align__(16) __half g_xh[N_ROWS][D];   // 64*x hi limb
__device__ __align__(16) __half g_xl[N_ROWS][D];   // 64*x lo limb
__device__ __align__(16) __half g_eh[K][D];        // 64*e hi limb (code-major)
__device__ __align__(16) __half g_el[K][D];        // 64*e lo limb
__device__ float g_codeT[K * D];
__device__ float g_norms[K];
__device__ int   g_counts[K];
__device__ int   g_idx[N_ROWS];
__device__ float g_partials[2048];

__device__ __forceinline__ uint32_t smem_u32(const void* p) {
    uint32_t a;
    asm("{ .reg .u64 t; cvta.to.shared.u64 t, %1; cvt.u32.u64 %0, t; }" : "=r"(a) : "l"(p));
    return a;
}
#define CP_ASYNC16(dst, src) \
    asm volatile("cp.async.cg.shared.global [%0], [%1], 16;" :: "r"(dst), "l"(src))
#define CP_COMMIT() asm volatile("cp.async.commit_group;" ::: "memory")
#define CP_WAIT(n)  asm volatile("cp.async.wait_group %0;" :: "n"(n) : "memory")
#define LDMATRIX4(r, a) \
    asm volatile("ldmatrix.sync.aligned.m8n8.x4.shared.b16 {%0,%1,%2,%3}, [%4];" \
        : "=r"((r)[0]), "=r"((r)[1]), "=r"((r)[2]), "=r"((r)[3]) : "r"(a))
#define MMA16816(c, a, b) \
    asm volatile("mma.sync.aligned.m16n8k16.row.col.f32.f16.f16.f32 " \
        "{%0,%1,%2,%3}, {%4,%5,%6,%7}, {%8,%9}, {%0,%1,%2,%3};" \
        : "+f"((c)[0]), "+f"((c)[1]), "+f"((c)[2]), "+f"((c)[3]) \
        : "r"((a)[0]), "r"((a)[1]), "r"((a)[2]), "r"((a)[3]), "r"((b)[0]), "r"((b)[1]))

// ---------------- prep kernels ----------------
__global__ void transpose_kernel(const float* __restrict__ cb) {
    __shared__ float tile[32][33];
    int k0 = blockIdx.x * 32, d0 = blockIdx.y * 32, x = threadIdx.x, y = threadIdx.y;
    #pragma unroll
    for (int i = 0; i < 32; i += 8) tile[y + i][x] = cb[(size_t)(d0 + y + i) * K + k0 + x];
    __syncthreads();
    #pragma unroll
    for (int i = 0; i < 32; i += 8) {
        int k = k0 + y + i, d = d0 + x;
        float v = tile[x][y + i];
        g_codeT[(size_t)k * D + d] = v;
        float vs = v * 64.0f;
        __half h = __float2half(vs);
        g_eh[k][d] = h;
        g_el[k][d] = __float2half(vs - __half2float(h));
    }
    if (blockIdx.y == 0 && threadIdx.y == 0) g_counts[k0 + x] = 0;
}

__global__ void norms_kernel() {
    __shared__ float s[256];
    int k = blockIdx.x, t = threadIdx.x;
    float v = g_codeT[(size_t)k * D + t];
    s[t] = v * v;
    __syncthreads();
    for (int r = 128; r > 0; r >>= 1) { if (t < r) s[t] += s[t + r]; __syncthreads(); }
    if (t == 0) g_norms[k] = s[0];
}

__global__ __launch_bounds__(256) void split_x_kernel(const float* __restrict__ X) {
    int i = blockIdx.x * 256 + threadIdx.x;
    int row = i >> 5, d0 = (i & 31) << 3;
    const float4* src = (const float4*)(X + (size_t)row * D + d0);
    float4 v0 = src[0], v1 = src[1];
    float vs[8] = {v0.x, v0.y, v0.z, v0.w, v1.x, v1.y, v1.z, v1.w};
    __align__(16) __half ph[8], pl[8];
    #pragma unroll
    for (int j = 0; j < 8; j++) {
        float v = vs[j] * 64.0f;
        __half h = __float2half(v);
        ph[j] = h;
        pl[j] = __float2half(v - __half2float(h));
    }
    *(uint4*)&g_xh[row][d0] = *(uint4*)ph;
    *(uint4*)&g_xl[row][d0] = *(uint4*)pl;
}

// ---------------- main: HMMA distance GEMM + fused argmin ----------------
// 512 threads = 16 warps: mwarp=wid&1 (64 rows), nwarp=wid>>1 (32 cols)
// CTA tile 128 rows x 256 cols, 8 col-tiles.
// A (xh,xl: 8 slabs x 16KB = 128KB) RESIDENT in smem.
// B streamed per 64-half chunk (32KB), 3 stages. eh chunks feed 2 passes
// (xh*eh, xl*eh) reusing B fragments; el chunks feed 1 pass (xh*el).
#define BOFF 131072
#define BSTG 32768
#define SMEMSZ (BOFF + 3 * BSTG)   // 229376

__device__ __forceinline__ void issue_b(uint32_t sb, int gb, int tid) {
    int ct = gb >> 3, bc = gb & 7, g = bc & 3;
    const char* base = (bc < 4) ? (const char*)g_eh : (const char*)g_el;
    uint32_t st = sb + BOFF + (gb % 3) * BSTG;
    #pragma unroll
    for (int j = 0; j < 4; j++) {
        int lin = j * 512 + tid;
        int row = lin >> 3, colb = (lin & 7) * 16;
        int off = row * 128 + colb;
        CP_ASYNC16(st + (off ^ ((off >> 3) & 0x70)),
                   base + (size_t)(ct * 256 + row) * 512 + g * 128 + colb);
    }
    CP_COMMIT();
}

__global__ __launch_bounds__(512, 1) void argmin_mma_kernel() {
    extern __shared__ char smem[];
    __shared__ unsigned long long sMin[128];
    uint32_t sb = smem_u32(smem);

    int tid = threadIdx.x, l = tid & 31, wid = tid >> 5;
    int mwarp = wid & 1, nwarp = wid >> 1;
    int row0 = blockIdx.x * 128;
    if (tid < 128) sMin[tid] = 0xFFFFFFFFFFFFFFFFULL;

    // A resident: 8 slabs (xh g=0..3, xl g=0..3), 128 rows x 128B each, SW128
    #pragma unroll
    for (int s = 0; s < 8; s++) {
        const char* base = (s < 4) ? (const char*)g_xh : (const char*)g_xl;
        int g = s & 3;
        #pragma unroll
        for (int j = 0; j < 2; j++) {
            int lin = j * 512 + tid;
            int row = lin >> 3, colb = (lin & 7) * 16;
            int off = row * 128 + colb;
            CP_ASYNC16(sb + s * 16384 + (off ^ ((off >> 3) & 0x70)),
                       base + (size_t)(row0 + row) * 512 + g * 128 + colb);
        }
    }
    CP_COMMIT();
    issue_b(sb, 0, tid);
    issue_b(sb, 1, tid);

    float best[4][2];
    int   bidx[4][2];
    #pragma unroll
    for (int a = 0; a < 4; a++)
        #pragma unroll
        for (int b = 0; b < 2; b++) { best[a][b] = 3.4e38f; bidx[a][b] = 0; }

    float acc[4][4][4];

    for (int gb = 0; gb < 64; gb++) {
        int ct = gb >> 3, bc = gb & 7, c0 = ct * 256;

        if (gb == 63) { CP_WAIT(0); } else { CP_WAIT(1); }
        __syncthreads();
        if (gb + 2 < 64) issue_b(sb, gb + 2, tid);

        if (bc == 0) {
            #pragma unroll
            for (int mf = 0; mf < 4; mf++)
                #pragma unroll
                for (int nf = 0; nf < 4; nf++)
                    #pragma unroll
                    for (int q = 0; q < 4; q++) acc[mf][nf][q] = 0.f;
        }

        uint32_t bBase = sb + BOFF + (gb % 3) * BSTG;
        int npass = (bc < 4) ? 2 : 1;

        #pragma unroll
        for (int ks = 0; ks < 4; ks++) {
            // B fragments: 32 cols, loaded ONCE, reused across A-limb passes
            uint32_t bfr[4][2];
            #pragma unroll
            for (int np = 0; np < 2; np++) {
                int code = nwarp * 32 + np * 16 + (l & 7) + ((l & 16) ? 8 : 0);
                int colb = ks * 32 + ((l & 8) ? 16 : 0);
                int off = code * 128 + colb;
                uint32_t r[4];
                LDMATRIX4(r, bBase + (off ^ ((off >> 3) & 0x70)));
                bfr[np * 2][0] = r[0]; bfr[np * 2][1] = r[1];
                bfr[np * 2 + 1][0] = r[2]; bfr[np * 2 + 1][1] = r[3];
            }
            for (int ps = 0; ps < npass; ps++) {
                int slab = (bc < 4) ? ((ps == 0) ? bc : bc + 4) : (bc - 4);
                uint32_t aBase = sb + slab * 16384;
                uint32_t afr[4][4];
                #pragma unroll
                for (int mf = 0; mf < 4; mf++) {
                    int row = mwarp * 64 + mf * 16 + (l & 15);
                    int colb = ks * 32 + ((l >> 4) << 4);
                    int off = row * 128 + colb;
                    LDMATRIX4(afr[mf], aBase + (off ^ ((off >> 3) & 0x70)));
                }
                #pragma unroll
                for (int mf = 0; mf < 4; mf++)
                    #pragma unroll
                    for (int nf = 0; nf < 4; nf++)
                        MMA16816(acc[mf][nf], afr[mf], bfr[nf]);
            }
        }

        if (bc == 7) {     // tile done: fused argmin epilogue (cols ascending)
            #pragma unroll
            for (int nf = 0; nf < 4; nf++) {
                int n0 = c0 + nwarp * 32 + nf * 8 + 2 * (l & 3);
                float nr0 = __ldg(&g_norms[n0]) * 4096.0f;
                float nr1 = __ldg(&g_norms[n0 + 1]) * 4096.0f;
                #pragma unroll
                for (int mf = 0; mf < 4; mf++) {
                    float d00 = fmaf(-2.0f, acc[mf][nf][0], nr0);
                    float d01 = fmaf(-2.0f, acc[mf][nf][1], nr1);
                    float d10 = fmaf(-2.0f, acc[mf][nf][2], nr0);
                    float d11 = fmaf(-2.0f, acc[mf][nf][3], nr1);
                    if (d00 < best[mf][0]) { best[mf][0] = d00; bidx[mf][0] = n0; }
                    if (d01 < best[mf][0]) { best[mf][0] = d01; bidx[mf][0] = n0 + 1; }
                    if (d10 < best[mf][1]) { best[mf][1] = d10; bidx[mf][1] = n0; }
                    if (d11 < best[mf][1]) { best[mf][1] = d11; bidx[mf][1] = n0 + 1; }
                }
            }
        }
    }

    // merge the 4 column-lanes (l&3), then packed atomicMin per row
    #pragma unroll
    for (int mf = 0; mf < 4; mf++)
        #pragma unroll
        for (int rh = 0; rh < 2; rh++) {
            float bv = best[mf][rh]; int bi = bidx[mf][rh];
            #pragma unroll
            for (int dlt = 1; dlt <= 2; dlt <<= 1) {
                float ov = __shfl_xor_sync(0xFFFFFFFFu, bv, dlt);
                int   oi = __shfl_xor_sync(0xFFFFFFFFu, bi, dlt);
                if (ov < bv || (ov == bv && oi < bi)) { bv = ov; bi = oi; }
            }
            if ((l & 3) == 0) {
                int row = mwarp * 64 + mf * 16 + rh * 8 + (l >> 2);
                uint32_t b = __float_as_uint(bv);
                b = (b & 0x80000000u) ? ~b : (b | 0x80000000u);   // monotone key
                unsigned long long key = ((unsigned long long)b << 32) | (uint32_t)bi;
                atomicMin(&sMin[row], key);
            }
        }
    __syncthreads();
    if (tid < 128) {
        int bi = (int)(uint32_t)(sMin[tid] & 0xFFFFFFFFULL);
        g_idx[row0 + tid] = bi;
        atomicAdd(&g_counts[bi], 1);
    }
}

// ---------------- epilogue kernels ----------------
__global__ __launch_bounds__(256) void quantize_kernel(const float* __restrict__ X,
                                                       float* __restrict__ out) {
    const int total4 = N_ROWS * D / 4;
    int stride = gridDim.x * blockDim.x;
    float sum = 0.f;
    for (int i = blockIdx.x * blockDim.x + threadIdx.x; i < total4; i += stride) {
        int row = i >> 6, d4 = (i & 63) << 2;
        float4 xv = ((const float4*)X)[i];
        float4 q = *(const float4*)&g_codeT[(size_t)g_idx[row] * D + d4];
        ((float4*)out)[i] = q;
        float dx = xv.x - q.x, dy = xv.y - q.y, dz = xv.z - q.z, dw = xv.w - q.w;
        sum += dx * dx + dy * dy + dz * dz + dw * dw;
    }
    __shared__ float s[256];
    s[threadIdx.x] = sum;
    __syncthreads();
    for (int r = 128; r > 0; r >>= 1) { if (threadIdx.x < r) s[threadIdx.x] += s[threadIdx.x + r]; __syncthreads(); }
    if (threadIdx.x == 0) g_partials[blockIdx.x] = s[0];
}

__global__ void finalize_kernel(float* __restrict__ out) {
    __shared__ double sd[256];
    int t = threadIdx.x;
    double s = 0.0;
    for (int i = t; i < 2048; i += 256) s += (double)g_partials[i];
    sd[t] = s;
    __syncthreads();
    for (int r = 128; r > 0; r >>= 1) { if (t < r) sd[t] += sd[t + r]; __syncthreads(); }
    double loss = 1.25 * sd[0] / (double)((long long)N_ROWS * D);
    __syncthreads();
    double h = 0.0;
    for (int i = t; i < K; i += 256) {
        double p = (double)g_counts[i] / (double)N_ROWS;
        h += p * log(p + 1e-10);
    }
    sd[t] = h;
    __syncthreads();
    for (int r = 128; r > 0; r >>= 1) { if (t < r) sd[t] += sd[t + r]; __syncthreads(); }
    if (t == 0) {
        out[(size_t)N_ROWS * D]     = (float)loss;
        out[(size_t)N_ROWS * D + 1] = (float)exp(-sd[0]);
    }
}

// ------------------------------------------------------------------
extern "C" void kernel_launch(void* const* d_in, const int* in_sizes, int n_in,
                              void* d_out, int out_size) {
    const float* x  = (const float*)d_in[0];
    const float* cb = (const float*)d_in[1];
    float* out = (float*)d_out;

    cudaFuncSetAttribute(argmin_mma_kernel,
                         cudaFuncAttributeMaxDynamicSharedMemorySize, SMEMSZ);

    transpose_kernel<<<dim3(K / 32, D / 32), dim3(32, 8)>>>(cb);
    norms_kernel<<<K, 256>>>();
    split_x_kernel<<<N_ROWS * D / 8 / 256, 256>>>(x);
    argmin_mma_kernel<<<N_ROWS / 128, 512, SMEMSZ>>>();
    quantize_kernel<<<2048, 256>>>(x, out);
    finalize_kernel<<<1, 256>>>(out);
}

// round 16
// speedup vs baseline: 1.3865x; 1.3865x over previous
#include <cuda_runtime.h>
#include <cuda_fp16.h>
#include <cstdint>
#include <math.h>

#define N_ROWS 65536
#define D      256
#define K      2048
#define NSLOT  32

// ---------------- device scratch ----------------
__device__ __align__(16) __half g_xh[N_ROWS][D];   // fp16(64*x)
__device__ __align__(16) __half g_eh[K][D];        // fp16(64*e), code-major
__device__ float  g_codeT[K * D];
__device__ float  g_norms[K];                      // ||e||^2 (unscaled)
__device__ float2 g_rowS[N_ROWS];                  // {||xh||, ||xl||} (64x scale)
__device__ int    g_maxTh, g_maxTl;                // ordered-int max of ||eh||,||el||
__device__ int    g_cnt[N_ROWS];
__device__ unsigned int g_cand[N_ROWS * NSLOT];
__device__ int    g_counts[K];
__device__ int    g_idx[N_ROWS];
__device__ float  g_partials[2048];

__device__ __forceinline__ uint32_t smem_u32(const void* p) {
    uint32_t a;
    asm("{ .reg .u64 t; cvta.to.shared.u64 t, %1; cvt.u32.u64 %0, t; }" : "=r"(a) : "l"(p));
    return a;
}
#define CP_ASYNC16(dst, src) \
    asm volatile("cp.async.cg.shared.global [%0], [%1], 16;" :: "r"(dst), "l"(src))
#define CP_COMMIT() asm volatile("cp.async.commit_group;" ::: "memory")
#define CP_WAIT(n)  asm volatile("cp.async.wait_group %0;" :: "n"(n) : "memory")
#define LDMATRIX4(r, a) \
    asm volatile("ldmatrix.sync.aligned.m8n8.x4.shared.b16 {%0,%1,%2,%3}, [%4];" \
        : "=r"((r)[0]), "=r"((r)[1]), "=r"((r)[2]), "=r"((r)[3]) : "r"(a))
#define MMA16816(c, a, b) \
    asm volatile("mma.sync.aligned.m16n8k16.row.col.f32.f16.f16.f32 " \
        "{%0,%1,%2,%3}, {%4,%5,%6,%7}, {%8,%9}, {%0,%1,%2,%3};" \
        : "+f"((c)[0]), "+f"((c)[1]), "+f"((c)[2]), "+f"((c)[3]) \
        : "r"((a)[0]), "r"((a)[1]), "r"((a)[2]), "r"((a)[3]), "r"((b)[0]), "r"((b)[1]))

__device__ __forceinline__ uint32_t fkey(float v) {       // monotone float->u32
    uint32_t b = __float_as_uint(v);
    return (b & 0x80000000u) ? ~b : (b | 0x80000000u);
}
__device__ __forceinline__ float funkey(uint32_t k) {
    return (k & 0x80000000u) ? __uint_as_float(k ^ 0x80000000u)
                             : __uint_as_float(~k);
}

// ---------------- prep kernels ----------------
__global__ void transpose_kernel(const float* __restrict__ cb) {
    __shared__ float tile[32][33];
    int k0 = blockIdx.x * 32, d0 = blockIdx.y * 32, x = threadIdx.x, y = threadIdx.y;
    #pragma unroll
    for (int i = 0; i < 32; i += 8) tile[y + i][x] = cb[(size_t)(d0 + y + i) * K + k0 + x];
    __syncthreads();
    #pragma unroll
    for (int i = 0; i < 32; i += 8) {
        int k = k0 + y + i, d = d0 + x;
        float v = tile[x][y + i];
        g_codeT[(size_t)k * D + d] = v;
        g_eh[k][d] = __float2half(v * 64.0f);
    }
    if (blockIdx.y == 0 && threadIdx.y == 0) g_counts[k0 + x] = 0;
}

// per-code: ||e||^2 -> g_norms; max ||eh||, ||el|| -> g_maxTh/Tl (ordered-int)
__global__ void norms_kernel() {
    __shared__ float s[256];
    int k = blockIdx.x, t = threadIdx.x;
    float v  = g_codeT[(size_t)k * D + t];
    float eh = __half2float(g_eh[k][t]);
    float el = __half2float(__float2half(v * 64.0f - eh));
    float n2 = v * v, h2 = eh * eh, l2 = el * el;
    s[t] = n2; __syncthreads();
    for (int r = 128; r > 0; r >>= 1) { if (t < r) s[t] += s[t + r]; __syncthreads(); }
    if (t == 0) g_norms[k] = s[0];
    __syncthreads();
    s[t] = h2; __syncthreads();
    for (int r = 128; r > 0; r >>= 1) { if (t < r) s[t] += s[t + r]; __syncthreads(); }
    if (t == 0) atomicMax(&g_maxTh, __float_as_int(sqrtf(s[0]) * 1.0001f + 1e-6f));
    __syncthreads();
    s[t] = l2; __syncthreads();
    for (int r = 128; r > 0; r >>= 1) { if (t < r) s[t] += s[t + r]; __syncthreads(); }
    if (t == 0) atomicMax(&g_maxTl, __float_as_int(sqrtf(s[0]) * 1.0001f + 1e-6f));
}

// split x -> xh; per-row {||xh||,||xl||}; zero g_cnt
__global__ __launch_bounds__(256) void split_x_kernel(const float* __restrict__ X) {
    int i = blockIdx.x * 256 + threadIdx.x;
    int row = i >> 5, d0 = (i & 31) << 3;
    const float4* src = (const float4*)(X + (size_t)row * D + d0);
    float4 v0 = src[0], v1 = src[1];
    float vs[8] = {v0.x, v0.y, v0.z, v0.w, v1.x, v1.y, v1.z, v1.w};
    __align__(16) __half ph[8];
    float sh2 = 0.f, sl2 = 0.f;
    #pragma unroll
    for (int j = 0; j < 8; j++) {
        float v = vs[j] * 64.0f;
        __half h = __float2half(v);
        float hf = __half2float(h);
        float lf = __half2float(__float2half(v - hf));
        ph[j] = h;
        sh2 += hf * hf;
        sl2 += lf * lf;
    }
    *(uint4*)&g_xh[row][d0] = *(uint4*)ph;
    #pragma unroll
    for (int d = 16; d > 0; d >>= 1) {
        sh2 += __shfl_xor_sync(0xFFFFFFFFu, sh2, d);
        sl2 += __shfl_xor_sync(0xFFFFFFFFu, sl2, d);
    }
    if ((i & 31) == 0) {
        g_rowS[row] = make_float2(sqrtf(sh2) * 1.0001f + 1e-6f,
                                  sqrtf(sl2) * 1.0001f + 1e-6f);
        g_cnt[row] = 0;
    }
}

// ---------------- phase 1: hi-limb HMMA GEMM + sound candidate filter ----------------
// 256 thr = 8 warps (mwarp 2 x nwarp 4), CTA 128 rows x 256-col tiles (8 tiles).
// A = xh resident (4 slabs x 16KB). B = eh streamed (32KB chunk, 3 stages).
#define BOFF 65536
#define BSTG 32768
#define SMEMSZ (BOFF + 3 * BSTG)   // 163840

__device__ __forceinline__ void issue_b(uint32_t sb, int gb, int tid) {
    int ct = gb >> 2, g = gb & 3;
    uint32_t st = sb + BOFF + (gb % 3) * BSTG;
    #pragma unroll
    for (int j = 0; j < 8; j++) {
        int lin = j * 256 + tid;
        int row = lin >> 3, colb = (lin & 7) * 16;
        int off = row * 128 + colb;
        CP_ASYNC16(st + (off ^ ((off >> 3) & 0x70)),
                   (const char*)g_eh + (size_t)(ct * 256 + row) * 512 + g * 128 + colb);
    }
    CP_COMMIT();
}

__global__ __launch_bounds__(256, 1) void phase1_kernel() {
    extern __shared__ char smem[];
    __shared__ uint32_t sMin[128];
    __shared__ float    sThr[128];
    __shared__ int      scnt[128];
    __shared__ unsigned int cand[128][NSLOT];
    uint32_t sb = smem_u32(smem);

    int tid = threadIdx.x, l = tid & 31, wid = tid >> 5;
    int mwarp = wid & 1, nwarp = wid >> 1;
    int row0 = blockIdx.x * 128;

    if (tid < 128) {
        sMin[tid] = 0xFFFFFFFFu;
        scnt[tid] = 0;
        float2 s = g_rowS[row0 + tid];
        float Th = __int_as_float(g_maxTh), Tl = __int_as_float(g_maxTl);
        sThr[tid] = 2.0f * (s.x * Tl + s.y * Th + s.y * Tl) + 256.0f;  // 2E + slack
    }

    // A resident: 4 slabs (xh chunk g), 128 rows x 128B, SW128
    #pragma unroll
    for (int g = 0; g < 4; g++) {
        #pragma unroll
        for (int j = 0; j < 4; j++) {
            int lin = j * 256 + tid;
            int row = lin >> 3, colb = (lin & 7) * 16;
            int off = row * 128 + colb;
            CP_ASYNC16(sb + g * 16384 + (off ^ ((off >> 3) & 0x70)),
                       (const char*)g_xh + (size_t)(row0 + row) * 512 + g * 128 + colb);
        }
    }
    CP_COMMIT();
    issue_b(sb, 0, tid);
    issue_b(sb, 1, tid);

    float acc[4][8][4];

    for (int gb = 0; gb < 32; gb++) {
        int ct = gb >> 2, bc = gb & 3, c0 = ct * 256;

        if (gb == 31) { CP_WAIT(0); } else { CP_WAIT(1); }
        __syncthreads();
        if (gb + 2 < 32) issue_b(sb, gb + 2, tid);

        if (bc == 0) {
            #pragma unroll
            for (int mf = 0; mf < 4; mf++)
                #pragma unroll
                for (int nf = 0; nf < 8; nf++)
                    #pragma unroll
                    for (int q = 0; q < 4; q++) acc[mf][nf][q] = 0.f;
        }

        uint32_t aBase = sb + bc * 16384;
        uint32_t bBase = sb + BOFF + (gb % 3) * BSTG;
        #pragma unroll
        for (int ks = 0; ks < 4; ks++) {
            uint32_t bfr[8][2];
            #pragma unroll
            for (int np = 0; np < 4; np++) {
                int code = nwarp * 64 + np * 16 + (l & 7) + ((l & 16) ? 8 : 0);
                int colb = ks * 32 + ((l & 8) ? 16 : 0);
                int off = code * 128 + colb;
                uint32_t r[4];
                LDMATRIX4(r, bBase + (off ^ ((off >> 3) & 0x70)));
                bfr[np * 2][0] = r[0]; bfr[np * 2][1] = r[1];
                bfr[np * 2 + 1][0] = r[2]; bfr[np * 2 + 1][1] = r[3];
            }
            uint32_t afr[4][4];
            #pragma unroll
            for (int mf = 0; mf < 4; mf++) {
                int row = mwarp * 64 + mf * 16 + (l & 15);
                int colb = ks * 32 + ((l >> 4) << 4);
                int off = row * 128 + colb;
                LDMATRIX4(afr[mf], aBase + (off ^ ((off >> 3) & 0x70)));
            }
            #pragma unroll
            for (int mf = 0; mf < 4; mf++)
                #pragma unroll
                for (int nf = 0; nf < 8; nf++)
                    MMA16816(acc[mf][nf], afr[mf], bfr[nf]);
        }

        if (bc == 3) {
            // pass a: per-row prefix-min over approx scaled distances
            #pragma unroll
            for (int nf = 0; nf < 8; nf++) {
                int n0 = c0 + nwarp * 64 + nf * 8 + 2 * (l & 3);
                float nr0 = __ldg(&g_norms[n0]) * 4096.0f;
                float nr1 = __ldg(&g_norms[n0 + 1]) * 4096.0f;
                #pragma unroll
                for (int mf = 0; mf < 4; mf++) {
                    int rl0 = mwarp * 64 + mf * 16 + (l >> 2);
                    float d00 = fmaf(-2.0f, acc[mf][nf][0], nr0);
                    float d01 = fmaf(-2.0f, acc[mf][nf][1], nr1);
                    float d10 = fmaf(-2.0f, acc[mf][nf][2], nr0);
                    float d11 = fmaf(-2.0f, acc[mf][nf][3], nr1);
                    atomicMin(&sMin[rl0],     fkey(fminf(d00, d01)));
                    atomicMin(&sMin[rl0 + 8], fkey(fminf(d10, d11)));
                }
            }
            __syncthreads();
            // pass b: collect codes within threshold of prefix-min (sound superset)
            #pragma unroll
            for (int nf = 0; nf < 8; nf++) {
                int n0 = c0 + nwarp * 64 + nf * 8 + 2 * (l & 3);
                float nr0 = __ldg(&g_norms[n0]) * 4096.0f;
                float nr1 = __ldg(&g_norms[n0 + 1]) * 4096.0f;
                #pragma unroll
                for (int mf = 0; mf < 4; mf++) {
                    #pragma unroll
                    for (int rh = 0; rh < 2; rh++) {
                        int rl = mwarp * 64 + mf * 16 + rh * 8 + (l >> 2);
                        float thr = funkey(sMin[rl]) + sThr[rl];
                        float da = fmaf(-2.0f, acc[mf][nf][rh * 2],     nr0);
                        float db = fmaf(-2.0f, acc[mf][nf][rh * 2 + 1], nr1);
                        if (da <= thr) {
                            int s = atomicAdd(&scnt[rl], 1);
                            if (s < NSLOT) cand[rl][s] = (unsigned)n0;
                        }
                        if (db <= thr) {
                            int s = atomicAdd(&scnt[rl], 1);
                            if (s < NSLOT) cand[rl][s] = (unsigned)(n0 + 1);
                        }
                    }
                }
            }
        }
    }
    __syncthreads();
    if (tid < 128) {
        int row = row0 + tid;
        int c = scnt[tid];
        g_cnt[row] = c;
        int n = c < NSLOT ? c : NSLOT;
        for (int s = 0; s < n; s++) g_cand[(size_t)row * NSLOT + s] = cand[tid][s];
    }
}

// ---------------- phase 2: exact fp32 re-rank (warp per row) ----------------
__global__ __launch_bounds__(256) void phase2_kernel(const float* __restrict__ X) {
    int gw = (blockIdx.x * 256 + threadIdx.x) >> 5;   // 0..65535
    int l = threadIdx.x & 31;
    int row = gw;

    float4 xa = *(const float4*)(X + (size_t)row * D + l * 8);
    float4 xb = *(const float4*)(X + (size_t)row * D + l * 8 + 4);

    float best = 3.4e38f;
    int   bi = 0;
    int cnt = g_cnt[row];
    int full = (cnt > NSLOT);
    int n = full ? K : cnt;

    for (int s = 0; s < n; s++) {
        int c = full ? s : (int)g_cand[(size_t)row * NSLOT + s];
        const float* cr = &g_codeT[(size_t)c * D + l * 8];
        float4 ca = *(const float4*)cr;
        float4 cb2 = *(const float4*)(cr + 4);
        float p = xa.x * ca.x + xa.y * ca.y + xa.z * ca.z + xa.w * ca.w
                + xb.x * cb2.x + xb.y * cb2.y + xb.z * cb2.z + xb.w * cb2.w;
        #pragma unroll
        for (int d = 16; d > 0; d >>= 1) p += __shfl_xor_sync(0xFFFFFFFFu, p, d);
        float dist = fmaf(-2.0f, p, __ldg(&g_norms[c]));
        if (dist < best || (dist == best && c < bi)) { best = dist; bi = c; }
    }
    if (l == 0) {
        g_idx[row] = bi;
        atomicAdd(&g_counts[bi], 1);
    }
}

// ---------------- epilogue kernels ----------------
__global__ __launch_bounds__(256) void quantize_kernel(const float* __restrict__ X,
                                                       float* __restrict__ out) {
    const int total4 = N_ROWS * D / 4;
    int stride = gridDim.x * blockDim.x;
    float sum = 0.f;
    for (int i = blockIdx.x * blockDim.x + threadIdx.x; i < total4; i += stride) {
        int row = i >> 6, d4 = (i & 63) << 2;
        float4 xv = ((const float4*)X)[i];
        float4 q = *(const float4*)&g_codeT[(size_t)g_idx[row] * D + d4];
        ((float4*)out)[i] = q;
        float dx = xv.x - q.x, dy = xv.y - q.y, dz = xv.z - q.z, dw = xv.w - q.w;
        sum += dx * dx + dy * dy + dz * dz + dw * dw;
    }
    __shared__ float s[256];
    s[threadIdx.x] = sum;
    __syncthreads();
    for (int r = 128; r > 0; r >>= 1) { if (threadIdx.x < r) s[threadIdx.x] += s[threadIdx.x + r]; __syncthreads(); }
    if (threadIdx.x == 0) g_partials[blockIdx.x] = s[0];
}

__global__ void finalize_kernel(float* __restrict__ out) {
    __shared__ double sd[256];
    int t = threadIdx.x;
    double s = 0.0;
    for (int i = t; i < 2048; i += 256) s += (double)g_partials[i];
    sd[t] = s;
    __syncthreads();
    for (int r = 128; r > 0; r >>= 1) { if (t < r) sd[t] += sd[t + r]; __syncthreads(); }
    double loss = 1.25 * sd[0] / (double)((long long)N_ROWS * D);
    __syncthreads();
    double h = 0.0;
    for (int i = t; i < K; i += 256) {
        double p = (double)g_counts[i] / (double)N_ROWS;
        h += p * log(p + 1e-10);
    }
    sd[t] = h;
    __syncthreads();
    for (int r = 128; r > 0; r >>= 1) { if (t < r) sd[t] += sd[t + r]; __syncthreads(); }
    if (t == 0) {
        out[(size_t)N_ROWS * D]     = (float)loss;
        out[(size_t)N_ROWS * D + 1] = (float)exp(-sd[0]);
    }
}

// ------------------------------------------------------------------
extern "C" void kernel_launch(void* const* d_in, const int* in_sizes, int n_in,
                              void* d_out, int out_size) {
    const float* x  = (const float*)d_in[0];
    const float* cb = (const float*)d_in[1];
    float* out = (float*)d_out;

    cudaFuncSetAttribute(phase1_kernel,
                         cudaFuncAttributeMaxDynamicSharedMemorySize, SMEMSZ);

    transpose_kernel<<<dim3(K / 32, D / 32), dim3(32, 8)>>>(cb);
    norms_kernel<<<K, 256>>>();
    split_x_kernel<<<N_ROWS * D / 8 / 256, 256>>>(x);
    phase1_kernel<<<N_ROWS / 128, 256, SMEMSZ>>>();
    phase2_kernel<<<N_ROWS / 8, 256>>>(x);
    quantize_kernel<<<2048, 256>>>(x, out);
    finalize_kernel<<<1, 256>>>(out);
}

// round 17
// speedup vs baseline: 1.6732x; 1.2068x over previous
#include <cuda_runtime.h>
#include <cuda_fp16.h>
#include <cstdint>
#include <math.h>

#define N_ROWS 65536
#define D      256
#define K      2048
#define NSLOT  32

// ---------------- device scratch ----------------
__device__ __align__(16) __half g_xh[N_ROWS][D];   // fp16(64*x)
__device__ __align__(16) __half g_eh[K][D];        // fp16(64*e), code-major
__device__ float  g_codeT[K * D];
__device__ float  g_norms[K];                      // ||e||^2 (unscaled)
__device__ float2 g_rowS[N_ROWS];                  // {||xh||, ||xl||} (64x scale)
__device__ int    g_maxTh, g_maxTl;                // ordered-int max of ||eh||,||el||
__device__ int    g_cnt[N_ROWS];
__device__ unsigned int g_cand[N_ROWS * NSLOT];
__device__ int    g_counts[K];
__device__ int    g_idx[N_ROWS];
__device__ float  g_partials[2048];

__device__ __forceinline__ uint32_t smem_u32(const void* p) {
    uint32_t a;
    asm("{ .reg .u64 t; cvta.to.shared.u64 t, %1; cvt.u32.u64 %0, t; }" : "=r"(a) : "l"(p));
    return a;
}
#define CP_ASYNC16(dst, src) \
    asm volatile("cp.async.cg.shared.global [%0], [%1], 16;" :: "r"(dst), "l"(src))
#define CP_COMMIT() asm volatile("cp.async.commit_group;" ::: "memory")
#define CP_WAIT(n)  asm volatile("cp.async.wait_group %0;" :: "n"(n) : "memory")
#define LDMATRIX4(r, a) \
    asm volatile("ldmatrix.sync.aligned.m8n8.x4.shared.b16 {%0,%1,%2,%3}, [%4];" \
        : "=r"((r)[0]), "=r"((r)[1]), "=r"((r)[2]), "=r"((r)[3]) : "r"(a))
#define MMA16816(c, a, b) \
    asm volatile("mma.sync.aligned.m16n8k16.row.col.f32.f16.f16.f32 " \
        "{%0,%1,%2,%3}, {%4,%5,%6,%7}, {%8,%9}, {%0,%1,%2,%3};" \
        : "+f"((c)[0]), "+f"((c)[1]), "+f"((c)[2]), "+f"((c)[3]) \
        : "r"((a)[0]), "r"((a)[1]), "r"((a)[2]), "r"((a)[3]), "r"((b)[0]), "r"((b)[1]))

__device__ __forceinline__ uint32_t fkey(float v) {       // monotone float->u32
    uint32_t b = __float_as_uint(v);
    return (b & 0x80000000u) ? ~b : (b | 0x80000000u);
}
__device__ __forceinline__ float funkey(uint32_t k) {
    return (k & 0x80000000u) ? __uint_as_float(k ^ 0x80000000u)
                             : __uint_as_float(~k);
}

// ---------------- prep kernels ----------------
__global__ void transpose_kernel(const float* __restrict__ cb) {
    __shared__ float tile[32][33];
    int k0 = blockIdx.x * 32, d0 = blockIdx.y * 32, x = threadIdx.x, y = threadIdx.y;
    #pragma unroll
    for (int i = 0; i < 32; i += 8) tile[y + i][x] = cb[(size_t)(d0 + y + i) * K + k0 + x];
    __syncthreads();
    #pragma unroll
    for (int i = 0; i < 32; i += 8) {
        int k = k0 + y + i, d = d0 + x;
        float v = tile[x][y + i];
        g_codeT[(size_t)k * D + d] = v;
        g_eh[k][d] = __float2half(v * 64.0f);
    }
    if (blockIdx.y == 0 && threadIdx.y == 0) g_counts[k0 + x] = 0;
}

// per-code: ||e||^2 -> g_norms; max ||eh||, ||el|| -> g_maxTh/Tl (ordered-int)
__global__ void norms_kernel() {
    __shared__ float s[256];
    int k = blockIdx.x, t = threadIdx.x;
    float v  = g_codeT[(size_t)k * D + t];
    float eh = __half2float(g_eh[k][t]);
    float el = __half2float(__float2half(v * 64.0f - eh));
    float n2 = v * v, h2 = eh * eh, l2 = el * el;
    s[t] = n2; __syncthreads();
    for (int r = 128; r > 0; r >>= 1) { if (t < r) s[t] += s[t + r]; __syncthreads(); }
    if (t == 0) g_norms[k] = s[0];
    __syncthreads();
    s[t] = h2; __syncthreads();
    for (int r = 128; r > 0; r >>= 1) { if (t < r) s[t] += s[t + r]; __syncthreads(); }
    if (t == 0) atomicMax(&g_maxTh, __float_as_int(sqrtf(s[0]) * 1.0001f + 1e-6f));
    __syncthreads();
    s[t] = l2; __syncthreads();
    for (int r = 128; r > 0; r >>= 1) { if (t < r) s[t] += s[t + r]; __syncthreads(); }
    if (t == 0) atomicMax(&g_maxTl, __float_as_int(sqrtf(s[0]) * 1.0001f + 1e-6f));
}

// split x -> xh; per-row {||xh||,||xl||}; zero g_cnt
__global__ __launch_bounds__(256) void split_x_kernel(const float* __restrict__ X) {
    int i = blockIdx.x * 256 + threadIdx.x;
    int row = i >> 5, d0 = (i & 31) << 3;
    const float4* src = (const float4*)(X + (size_t)row * D + d0);
    float4 v0 = src[0], v1 = src[1];
    float vs[8] = {v0.x, v0.y, v0.z, v0.w, v1.x, v1.y, v1.z, v1.w};
    __align__(16) __half ph[8];
    float sh2 = 0.f, sl2 = 0.f;
    #pragma unroll
    for (int j = 0; j < 8; j++) {
        float v = vs[j] * 64.0f;
        __half h = __float2half(v);
        float hf = __half2float(h);
        float lf = __half2float(__float2half(v - hf));
        ph[j] = h;
        sh2 += hf * hf;
        sl2 += lf * lf;
    }
    *(uint4*)&g_xh[row][d0] = *(uint4*)ph;
    #pragma unroll
    for (int d = 16; d > 0; d >>= 1) {
        sh2 += __shfl_xor_sync(0xFFFFFFFFu, sh2, d);
        sl2 += __shfl_xor_sync(0xFFFFFFFFu, sl2, d);
    }
    if ((i & 31) == 0) {
        g_rowS[row] = make_float2(sqrtf(sh2) * 1.0001f + 1e-6f,
                                  sqrtf(sl2) * 1.0001f + 1e-6f);
        g_cnt[row] = 0;
    }
}

// ---------------- phase 1: hi-limb HMMA GEMM + sound candidate filter ----------------
// 256 thr = 8 warps (mwarp 2 x nwarp 4), CTA 128 rows x 256-col tiles (8 tiles).
// A = xh resident (4 slabs x 16KB). B = eh streamed (32KB chunk, 3 stages).
#define BOFF 65536
#define BSTG 32768
#define SMEMSZ (BOFF + 3 * BSTG)   // 163840

__device__ __forceinline__ void issue_b(uint32_t sb, int gb, int tid) {
    int ct = gb >> 2, g = gb & 3;
    uint32_t st = sb + BOFF + (gb % 3) * BSTG;
    #pragma unroll
    for (int j = 0; j < 8; j++) {
        int lin = j * 256 + tid;
        int row = lin >> 3, colb = (lin & 7) * 16;
        int off = row * 128 + colb;
        CP_ASYNC16(st + (off ^ ((off >> 3) & 0x70)),
                   (const char*)g_eh + (size_t)(ct * 256 + row) * 512 + g * 128 + colb);
    }
    CP_COMMIT();
}

__global__ __launch_bounds__(256, 1) void phase1_kernel() {
    extern __shared__ char smem[];
    __shared__ uint32_t sMin[128];
    __shared__ float    sThr[128];
    __shared__ int      scnt[128];
    __shared__ unsigned int cand[128][NSLOT];
    uint32_t sb = smem_u32(smem);

    int tid = threadIdx.x, l = tid & 31, wid = tid >> 5;
    int mwarp = wid & 1, nwarp = wid >> 1;
    int row0 = blockIdx.x * 128;

    if (tid < 128) {
        sMin[tid] = 0xFFFFFFFFu;
        scnt[tid] = 0;
        float2 s = g_rowS[row0 + tid];
        float Th = __int_as_float(g_maxTh), Tl = __int_as_float(g_maxTl);
        sThr[tid] = 2.0f * (s.x * Tl + s.y * Th + s.y * Tl) + 256.0f;  // 2E + slack
    }

    // A resident: 4 slabs (xh chunk g), 128 rows x 128B, SW128
    #pragma unroll
    for (int g = 0; g < 4; g++) {
        #pragma unroll
        for (int j = 0; j < 4; j++) {
            int lin = j * 256 + tid;
            int row = lin >> 3, colb = (lin & 7) * 16;
            int off = row * 128 + colb;
            CP_ASYNC16(sb + g * 16384 + (off ^ ((off >> 3) & 0x70)),
                       (const char*)g_xh + (size_t)(row0 + row) * 512 + g * 128 + colb);
        }
    }
    CP_COMMIT();
    issue_b(sb, 0, tid);
    issue_b(sb, 1, tid);

    float acc[4][8][4];

    for (int gb = 0; gb < 32; gb++) {
        int ct = gb >> 2, bc = gb & 3, c0 = ct * 256;

        if (gb == 31) { CP_WAIT(0); } else { CP_WAIT(1); }
        __syncthreads();
        if (gb + 2 < 32) issue_b(sb, gb + 2, tid);

        if (bc == 0) {
            #pragma unroll
            for (int mf = 0; mf < 4; mf++)
                #pragma unroll
                for (int nf = 0; nf < 8; nf++)
                    #pragma unroll
                    for (int q = 0; q < 4; q++) acc[mf][nf][q] = 0.f;
        }

        uint32_t aBase = sb + bc * 16384;
        uint32_t bBase = sb + BOFF + (gb % 3) * BSTG;
        #pragma unroll
        for (int ks = 0; ks < 4; ks++) {
            uint32_t bfr[8][2];
            #pragma unroll
            for (int np = 0; np < 4; np++) {
                int code = nwarp * 64 + np * 16 + (l & 7) + ((l & 16) ? 8 : 0);
                int colb = ks * 32 + ((l & 8) ? 16 : 0);
                int off = code * 128 + colb;
                uint32_t r[4];
                LDMATRIX4(r, bBase + (off ^ ((off >> 3) & 0x70)));
                bfr[np * 2][0] = r[0]; bfr[np * 2][1] = r[1];
                bfr[np * 2 + 1][0] = r[2]; bfr[np * 2 + 1][1] = r[3];
            }
            uint32_t afr[4][4];
            #pragma unroll
            for (int mf = 0; mf < 4; mf++) {
                int row = mwarp * 64 + mf * 16 + (l & 15);
                int colb = ks * 32 + ((l >> 4) << 4);
                int off = row * 128 + colb;
                LDMATRIX4(afr[mf], aBase + (off ^ ((off >> 3) & 0x70)));
            }
            #pragma unroll
            for (int mf = 0; mf < 4; mf++)
                #pragma unroll
                for (int nf = 0; nf < 8; nf++)
                    MMA16816(acc[mf][nf], afr[mf], bfr[nf]);
        }

        if (bc == 3) {
            // pass a: convert acc -> scaled distances IN PLACE; register-local
            // min per (mf, rh); ONE shared atomicMin per (mf, rh).
            float lmin[4][2];
            #pragma unroll
            for (int mf = 0; mf < 4; mf++) { lmin[mf][0] = 3.4e38f; lmin[mf][1] = 3.4e38f; }
            #pragma unroll
            for (int nf = 0; nf < 8; nf++) {
                int n0 = c0 + nwarp * 64 + nf * 8 + 2 * (l & 3);
                float nr0 = __ldg(&g_norms[n0]) * 4096.0f;
                float nr1 = __ldg(&g_norms[n0 + 1]) * 4096.0f;
                #pragma unroll
                for (int mf = 0; mf < 4; mf++) {
                    float d00 = fmaf(-2.0f, acc[mf][nf][0], nr0);
                    float d01 = fmaf(-2.0f, acc[mf][nf][1], nr1);
                    float d10 = fmaf(-2.0f, acc[mf][nf][2], nr0);
                    float d11 = fmaf(-2.0f, acc[mf][nf][3], nr1);
                    acc[mf][nf][0] = d00; acc[mf][nf][1] = d01;
                    acc[mf][nf][2] = d10; acc[mf][nf][3] = d11;
                    lmin[mf][0] = fminf(lmin[mf][0], fminf(d00, d01));
                    lmin[mf][1] = fminf(lmin[mf][1], fminf(d10, d11));
                }
            }
            #pragma unroll
            for (int mf = 0; mf < 4; mf++)
                #pragma unroll
                for (int rh = 0; rh < 2; rh++) {
                    int rl = mwarp * 64 + mf * 16 + rh * 8 + (l >> 2);
                    atomicMin(&sMin[rl], fkey(lmin[mf][rh]));
                }
            __syncthreads();
            // pass b: hoist thresholds to registers, then pure compares on acc
            float thr[4][2];
            #pragma unroll
            for (int mf = 0; mf < 4; mf++)
                #pragma unroll
                for (int rh = 0; rh < 2; rh++) {
                    int rl = mwarp * 64 + mf * 16 + rh * 8 + (l >> 2);
                    thr[mf][rh] = funkey(sMin[rl]) + sThr[rl];
                }
            #pragma unroll
            for (int nf = 0; nf < 8; nf++) {
                int n0 = c0 + nwarp * 64 + nf * 8 + 2 * (l & 3);
                #pragma unroll
                for (int mf = 0; mf < 4; mf++) {
                    #pragma unroll
                    for (int rh = 0; rh < 2; rh++) {
                        int rl = mwarp * 64 + mf * 16 + rh * 8 + (l >> 2);
                        if (acc[mf][nf][rh * 2] <= thr[mf][rh]) {
                            int s = atomicAdd(&scnt[rl], 1);
                            if (s < NSLOT) cand[rl][s] = (unsigned)n0;
                        }
                        if (acc[mf][nf][rh * 2 + 1] <= thr[mf][rh]) {
                            int s = atomicAdd(&scnt[rl], 1);
                            if (s < NSLOT) cand[rl][s] = (unsigned)(n0 + 1);
                        }
                    }
                }
            }
        }
    }
    __syncthreads();
    if (tid < 128) {
        int row = row0 + tid;
        int c = scnt[tid];
        g_cnt[row] = c;
        int n = c < NSLOT ? c : NSLOT;
        for (int s = 0; s < n; s++) g_cand[(size_t)row * NSLOT + s] = cand[tid][s];
    }
}

// ---------------- phase 2: exact fp32 re-rank (warp per row) ----------------
__global__ __launch_bounds__(256) void phase2_kernel(const float* __restrict__ X) {
    int gw = (blockIdx.x * 256 + threadIdx.x) >> 5;   // 0..65535
    int l = threadIdx.x & 31;
    int row = gw;

    float4 xa = *(const float4*)(X + (size_t)row * D + l * 8);
    float4 xb = *(const float4*)(X + (size_t)row * D + l * 8 + 4);

    float best = 3.4e38f;
    int   bi = 0;
    int cnt = g_cnt[row];
    int full = (cnt > NSLOT);
    int n = full ? K : cnt;

    for (int s = 0; s < n; s++) {
        int c = full ? s : (int)g_cand[(size_t)row * NSLOT + s];
        const float* cr = &g_codeT[(size_t)c * D + l * 8];
        float4 ca = *(const float4*)cr;
        float4 cb2 = *(const float4*)(cr + 4);
        float p = xa.x * ca.x + xa.y * ca.y + xa.z * ca.z + xa.w * ca.w
                + xb.x * cb2.x + xb.y * cb2.y + xb.z * cb2.z + xb.w * cb2.w;
        #pragma unroll
        for (int d = 16; d > 0; d >>= 1) p += __shfl_xor_sync(0xFFFFFFFFu, p, d);
        float dist = fmaf(-2.0f, p, __ldg(&g_norms[c]));
        if (dist < best || (dist == best && c < bi)) { best = dist; bi = c; }
    }
    if (l == 0) {
        g_idx[row] = bi;
        atomicAdd(&g_counts[bi], 1);
    }
}

// ---------------- epilogue kernels ----------------
__global__ __launch_bounds__(256) void quantize_kernel(const float* __restrict__ X,
                                                       float* __restrict__ out) {
    const int total4 = N_ROWS * D / 4;
    int stride = gridDim.x * blockDim.x;
    float sum = 0.f;
    for (int i = blockIdx.x * blockDim.x + threadIdx.x; i < total4; i += stride) {
        int row = i >> 6, d4 = (i & 63) << 2;
        float4 xv = ((const float4*)X)[i];
        float4 q = *(const float4*)&g_codeT[(size_t)g_idx[row] * D + d4];
        ((float4*)out)[i] = q;
        float dx = xv.x - q.x, dy = xv.y - q.y, dz = xv.z - q.z, dw = xv.w - q.w;
        sum += dx * dx + dy * dy + dz * dz + dw * dw;
    }
    __shared__ float s[256];
    s[threadIdx.x] = sum;
    __syncthreads();
    for (int r = 128; r > 0; r >>= 1) { if (threadIdx.x < r) s[threadIdx.x] += s[threadIdx.x + r]; __syncthreads(); }
    if (threadIdx.x == 0) g_partials[blockIdx.x] = s[0];
}

__global__ void finalize_kernel(float* __restrict__ out) {
    __shared__ double sd[256];
    int t = threadIdx.x;
    double s = 0.0;
    for (int i = t; i < 2048; i += 256) s += (double)g_partials[i];
    sd[t] = s;
    __syncthreads();
    for (int r = 128; r > 0; r >>= 1) { if (t < r) sd[t] += sd[t + r]; __syncthreads(); }
    double loss = 1.25 * sd[0] / (double)((long long)N_ROWS * D);
    __syncthreads();
    double h = 0.0;
    for (int i = t; i < K; i += 256) {
        double p = (double)g_counts[i] / (double)N_ROWS;
        h += p * log(p + 1e-10);
    }
    sd[t] = h;
    __syncthreads();
    for (int r = 128; r > 0; r >>= 1) { if (t < r) sd[t] += sd[t + r]; __syncthreads(); }
    if (t == 0) {
        out[(size_t)N_ROWS * D]     = (float)loss;
        out[(size_t)N_ROWS * D + 1] = (float)exp(-sd[0]);
    }
}

// ------------------------------------------------------------------
extern "C" void kernel_launch(void* const* d_in, const int* in_sizes, int n_in,
                              void* d_out, int out_size) {
    const float* x  = (const float*)d_in[0];
    const float* cb = (const float*)d_in[1];
    float* out = (float*)d_out;

    cudaFuncSetAttribute(phase1_kernel,
                         cudaFuncAttributeMaxDynamicSharedMemorySize, SMEMSZ);

    transpose_kernel<<<dim3(K / 32, D / 32), dim3(32, 8)>>>(cb);
    norms_kernel<<<K, 256>>>();
    split_x_kernel<<<N_ROWS * D / 8 / 256, 256>>>(x);
    phase1_kernel<<<N_ROWS / 128, 256, SMEMSZ>>>();
    phase2_kernel<<<N_ROWS / 8, 256>>>(x);
    quantize_kernel<<<2048, 256>>>(x, out);
    finalize_kernel<<<1, 256>>>(out);
}